// round 13
// baseline (speedup 1.0000x reference)
#include <cuda_runtime.h>
#include <math.h>

#define NLOC 196
#define PI_F 3.14159265358979323846f
#define FPSCALE 1048576.0f          // 2^20
#define INV_FPSCALE (1.0f/1048576.0f)

// Global accumulators / precomputed data (allocation-free rule: __device__ globals)
__device__ unsigned long long g_S[NLOC];   // sum   * 2^20 (int64)
__device__ unsigned long long g_Q[NLOC];   // sumsq * 2^20 (int64)
__device__ float4 g_W[81];                 // z = W * (1,C0,S0)x(1,C1,S1)x(1,C2,S2)x(1,C3,S3)

// spread bits of 4-bit x: bit i -> bit 2i
__device__ __forceinline__ int spread4(int x) {
    return (x & 1) | ((x & 2) << 1) | ((x & 4) << 2) | ((x & 8) << 3);
}

// One wire contraction of the pair-tensor: last base-4 digit (pair p=2k+k')
// -> base-3 digit m over (1, C, S) basis:
//   m=0: 0.5*(x00+x11)   m=1: 0.5*(x00-x11)   m=2: 0.5*(x01+x10)
#define CSTEP(IN, OUT, NB, NM)                                         \
  do {                                                                 \
    const int cnt = (NB) * 3 * (NM);                                   \
    for (int e = tid; e < 4 * cnt; e += 256) {                         \
      int i = e / cnt; int o = e - i * cnt;                            \
      int M = o % (NM); int rest = o / (NM);                           \
      int m = rest % 3; int B = rest / 3;                              \
      float x0 = IN[i][(B * 4 + 0) * (NM) + M];                        \
      float x1 = IN[i][(B * 4 + 1) * (NM) + M];                        \
      float x2 = IN[i][(B * 4 + 2) * (NM) + M];                        \
      float x3 = IN[i][(B * 4 + 3) * (NM) + M];                        \
      float rV;                                                        \
      if (m == 0)      rV = 0.5f * (x0 + x3);                          \
      else if (m == 1) rV = 0.5f * (x0 - x3);                          \
      else             rV = 0.5f * (x1 + x2);                          \
      OUT[i][o] = rV;                                                  \
    }                                                                  \
    __syncthreads();                                                   \
  } while (0)

// ---------------------------------------------------------------------------
// K1: blocks 0..127 — batch-major stats (4 batches each, coalesced float4
//     reads, packed int64 fixed-point smem atomics, then global int64 atomics;
//     integer adds => deterministic).
//     block 128 — build W (4 x 81) from params and store to global.
// Wire j <-> bit (3-j) of state index K.
// ---------------------------------------------------------------------------
__global__ void __launch_bounds__(256) qf_stats_w(const float* __restrict__ x,
                                                  const float* __restrict__ params) {
    const int tid = threadIdx.x;

    if (blockIdx.x < 128) {
        __shared__ unsigned long long accP[NLOC];   // (sum<<32 | sumsq), both *2^20
        for (int e = tid; e < NLOC; e += 256) accP[e] = 0ULL;
        __syncthreads();

        // 4 batches = 3136 floats = 784 float4, all coalesced
        for (int i = tid; i < 784; i += 256) {
            float4 v = reinterpret_cast<const float4*>(x)[blockIdx.x * 784 + i];
            int idx4 = i % 196;                 // float4 index within its batch
            int off  = idx4 * 4;                // starting col-flat offset (same row)
            int row  = off / 28;
            int cq   = off - row * 28;          // cols cq..cq+3
            int loc  = (row >> 1) * 14 + (cq >> 1);
            long long s0 = __float2ll_rn((v.x + v.y) * FPSCALE);
            long long q0 = __float2ll_rn((v.x * v.x + v.y * v.y) * FPSCALE);
            long long s1 = __float2ll_rn((v.z + v.w) * FPSCALE);
            long long q1 = __float2ll_rn((v.z * v.z + v.w * v.w) * FPSCALE);
            // q partial sums stay < 2^31 per block-location => no carry into s
            atomicAdd(&accP[loc],     (unsigned long long)((s0 << 32) + q0));
            atomicAdd(&accP[loc + 1], (unsigned long long)((s1 << 32) + q1));
        }
        __syncthreads();

        for (int e = tid; e < NLOC; e += 256) {
            unsigned long long P = accP[e];
            long long sI = (long long)(int)(P >> 32);              // sign-extend
            long long qI = (long long)(P & 0xffffffffULL);
            atomicAdd(&g_S[e], (unsigned long long)sI);
            atomicAdd(&g_Q[e], (unsigned long long)qI);
        }
    } else {
        // ---- W build (identical math to R12 phases 2a-2c) ----
        __shared__ float sP[16 * 17], sQ[16 * 17];
        __shared__ float bufA[4][256], bufB[4][256];

        // Phase 2a: U via shuffle butterflies; thread = (col, K)
        {
            const int col = tid >> 4, K = tid & 15;
            float vr = (K == col) ? 1.f : 0.f, vi = 0.f;
            #pragma unroll
            for (int l = 0; l < 2; l++) {
                #pragma unroll
                for (int wi = 0; wi < 4; wi++) {   // RY(params[l][w][0])
                    float ss, cc; __sincosf(0.5f * params[(l * 4 + wi) * 3 + 0], &ss, &cc);
                    int m = 8 >> wi;
                    float orr = __shfl_xor_sync(0xffffffffu, vr, m);
                    float oii = __shfl_xor_sync(0xffffffffu, vi, m);
                    if (K & m) { vr = fmaf(ss, orr, cc * vr);  vi = fmaf(ss, oii, cc * vi); }
                    else       { vr = fmaf(-ss, orr, cc * vr); vi = fmaf(-ss, oii, cc * vi); }
                }
                #pragma unroll
                for (int i = 0; i < 3; i++) {      // CNOT(i -> i+1)
                    int cm = 8 >> i, tm = 8 >> (i + 1);
                    float orr = __shfl_xor_sync(0xffffffffu, vr, tm);
                    float oii = __shfl_xor_sync(0xffffffffu, vi, tm);
                    if (K & cm) { vr = orr; vi = oii; }
                }
                #pragma unroll
                for (int wi = 0; wi < 4; wi++) {   // RY(params[l][w][1])
                    float ss, cc; __sincosf(0.5f * params[(l * 4 + wi) * 3 + 1], &ss, &cc);
                    int m = 8 >> wi;
                    float orr = __shfl_xor_sync(0xffffffffu, vr, m);
                    float oii = __shfl_xor_sync(0xffffffffu, vi, m);
                    if (K & m) { vr = fmaf(ss, orr, cc * vr);  vi = fmaf(ss, oii, cc * vi); }
                    else       { vr = fmaf(-ss, orr, cc * vr); vi = fmaf(-ss, oii, cc * vi); }
                }
                #pragma unroll
                for (int i = 0; i < 3; i++) {      // CNOT(i+1 -> i)
                    int cm = 8 >> (i + 1), tm = 8 >> i;
                    float orr = __shfl_xor_sync(0xffffffffu, vr, tm);
                    float oii = __shfl_xor_sync(0xffffffffu, vi, tm);
                    if (K & cm) { vr = orr; vi = oii; }
                }
                #pragma unroll
                for (int wi = 0; wi < 4; wi++) {   // RZ(params[l][w][2])
                    float ss, cc; __sincosf(0.5f * params[(l * 4 + wi) * 3 + 2], &ss, &cc);
                    int m = 8 >> wi;
                    float rr = vr, ii = vi;
                    if (K & m) { vr = rr * cc - ii * ss; vi = ii * cc + rr * ss; }
                    else       { vr = rr * cc + ii * ss; vi = ii * cc - rr * ss; }
                }
            }
            sP[K * 17 + col] = vr;
            sQ[K * 17 + col] = vi;
        }
        __syncthreads();

        // Phase 2b: A_i[k,k'] at interleaved base-4 pair index
        {
            const int k = tid >> 4, kp = tid & 15;
            float A0 = 0.f, A1 = 0.f, A2 = 0.f, A3 = 0.f;
            #pragma unroll
            for (int K = 0; K < 16; K++) {
                float pp = fmaf(sP[K * 17 + k], sP[K * 17 + kp],
                                sQ[K * 17 + k] * sQ[K * 17 + kp]);
                if (K & 8) A0 -= pp; else A0 += pp;
                if (K & 4) A1 -= pp; else A1 += pp;
                if (K & 2) A2 -= pp; else A2 += pp;
                if (K & 1) A3 -= pp; else A3 += pp;
            }
            int pi = 2 * spread4(k) + spread4(kp);
            bufA[0][pi] = A0; bufA[1][pi] = A1; bufA[2][pi] = A2; bufA[3][pi] = A3;
        }
        __syncthreads();

        // Phase 2c: contract 4 wires: 256 -> 192 -> 144 -> 108 -> 81
        CSTEP(bufA, bufB, 64, 1);
        CSTEP(bufB, bufA, 16, 3);
        CSTEP(bufA, bufB, 4, 9);
        CSTEP(bufB, bufA, 1, 27);

        if (tid < 81)
            g_W[tid] = make_float4(bufA[0][tid], bufA[1][tid], bufA[2][tid], bufA[3][tid]);
    }
}

// ---------------------------------------------------------------------------
// K2: one block per batch (512 blocks, 224 threads). Stage x[b] coalesced,
// load W, thread p (<196) = one patch location: finalize stats, 4 __sincosf
// (FULL angles), z = W * (v01 x v23). Coalesced float4 output.
// ---------------------------------------------------------------------------
__global__ void __launch_bounds__(224) qf_eval(const float* __restrict__ x,
                                               float* __restrict__ out) {
    __shared__ float  sx[784];
    __shared__ float4 sWk[81];
    const int tid = threadIdx.x;
    const int b = blockIdx.x;

    if (tid < 196)
        reinterpret_cast<float4*>(sx)[tid] = reinterpret_cast<const float4*>(x)[b * 196 + tid];
    if (tid < 81)
        sWk[tid] = g_W[tid];

    float mean = 0.f, scale = 0.f;
    if (tid < 196) {
        float S = (float)(long long)g_S[tid] * INV_FPSCALE;
        float Q = (float)(long long)g_Q[tid] * INV_FPSCALE;
        mean = S * (1.f / 2048.f);
        float ssd = Q - S * S * (1.f / 2048.f);
        float sd  = sqrtf(ssd * (1.f / 2047.f));
        scale = __fdividef(PI_F, sd + 1e-8f);
    }
    __syncthreads();
    if (tid >= 196) return;

    const int r = tid / 14, c = tid - r * 14;
    float2 u  = *reinterpret_cast<float2*>(&sx[(2 * r) * 28 + 2 * c]);
    float2 w2 = *reinterpret_cast<float2*>(&sx[(2 * r + 1) * 28 + 2 * c]);

    float C0, S0, C1, S1, C2, S2, C3, S3;
    __sincosf((u.x  - mean) * scale, &S0, &C0);
    __sincosf((u.y  - mean) * scale, &S1, &C1);
    __sincosf((w2.x - mean) * scale, &S2, &C2);
    __sincosf((w2.y - mean) * scale, &S3, &C3);

    float v01[9], v23[9];
    v01[0] = 1.f; v01[1] = C1;      v01[2] = S1;
    v01[3] = C0;  v01[4] = C0 * C1; v01[5] = C0 * S1;
    v01[6] = S0;  v01[7] = S0 * C1; v01[8] = S0 * S1;
    v23[0] = 1.f; v23[1] = C3;      v23[2] = S3;
    v23[3] = C2;  v23[4] = C2 * C3; v23[5] = C2 * S3;
    v23[6] = S2;  v23[7] = S2 * C3; v23[8] = S2 * S3;

    float z0 = 0.f, z1 = 0.f, z2 = 0.f, z3 = 0.f;
    #pragma unroll
    for (int al = 0; al < 9; al++) {
        float t0 = 0.f, t1 = 0.f, t2 = 0.f, t3 = 0.f;
        #pragma unroll
        for (int be = 0; be < 9; be++) {
            float4 wv = sWk[al * 9 + be];      // LDS.128 broadcast
            float vb = v23[be];
            t0 = fmaf(wv.x, vb, t0); t1 = fmaf(wv.y, vb, t1);
            t2 = fmaf(wv.z, vb, t2); t3 = fmaf(wv.w, vb, t3);
        }
        float ca = v01[al];
        z0 = fmaf(ca, t0, z0); z1 = fmaf(ca, t1, z1);
        z2 = fmaf(ca, t2, z2); z3 = fmaf(ca, t3, z3);
    }

    // out[b, p*4 + i] — contiguous per block => perfectly coalesced STG.128
    reinterpret_cast<float4*>(out)[b * 196 + tid] = make_float4(z0, z1, z2, z3);
}

extern "C" void kernel_launch(void* const* d_in, const int* in_sizes, int n_in,
                              void* d_out, int out_size) {
    const float* x      = (const float*)d_in[0];   // (512, 28, 28)
    const float* params = (const float*)d_in[1];   // (2, 4, 3)
    float* out          = (float*)d_out;           // (512, 784)

    void* pS = 0; void* pQ = 0;
    cudaGetSymbolAddress(&pS, g_S);
    cudaGetSymbolAddress(&pQ, g_Q);
    cudaMemsetAsync(pS, 0, NLOC * sizeof(unsigned long long));
    cudaMemsetAsync(pQ, 0, NLOC * sizeof(unsigned long long));

    qf_stats_w<<<129, 256>>>(x, params);
    qf_eval<<<512, 224>>>(x, out);
}